// round 2
// baseline (speedup 1.0000x reference)
#include <cuda_runtime.h>
#include <math.h>

#define BB 8
#define TT 512
#define RFF 16
#define HID 64
#define NH 16
#define TBL_N 65536   /* intervals; nodes 0..TBL_N inclusive */
#define TWO_PI_F 6.283185307179586f

// LUT: g_tbl[node][head], 16 fp32 per row (64B). (TBL_N + 2) rows so the
// clamped top index can still vector-read rows i and i+1.
__device__ __align__(128) static float g_tbl[(TBL_N + 2) * NH];

// ---------------------------------------------------------------------------
// Build kernel: evaluate the exact reference pipeline at each node d = i/TBL_N.
// One node per thread; weights staged in shared memory (uniform broadcast reads).
// ---------------------------------------------------------------------------
__global__ void __launch_bounds__(256) build_table_kernel(
    const float* __restrict__ phase,   // [16]
    const float* __restrict__ W1,      // [32,64]
    const float* __restrict__ b1,      // [64]
    const float* __restrict__ W2,      // [64,16]
    const float* __restrict__ b2)      // [16]
{
    __shared__ float sW1[2 * RFF * HID];
    __shared__ float sW2[HID * NH];
    __shared__ float sb1[HID];
    __shared__ float sb2[NH];
    __shared__ float sph[RFF];

    const int tid = threadIdx.x;
    for (int i = tid; i < 2 * RFF * HID; i += blockDim.x) sW1[i] = W1[i];
    for (int i = tid; i < HID * NH;     i += blockDim.x) sW2[i] = W2[i];
    if (tid < HID) sb1[tid] = b1[tid];
    if (tid < NH)  sb2[tid] = b2[tid];
    if (tid < RFF) sph[tid] = phase[tid];
    __syncthreads();

    const int node = blockIdx.x * blockDim.x + tid;
    if (node > TBL_N) return;

    const float d = (float)node * (1.0f / (float)TBL_N);

    // RFF frequencies: logspace(log10 2, log10 64, 16) = 2^(1 + k/3)
    float feats[2 * RFF];
#pragma unroll
    for (int k = 0; k < RFF; k++) {
        const float f = exp2f(1.0f + (float)k * (1.0f / 3.0f));
        const float a = fmaf(TWO_PI_F * f, d, sph[k]);
        float s, c;
        sincosf(a, &s, &c);
        feats[k]       = s;
        feats[RFF + k] = c;
    }

    float o[NH];
#pragma unroll
    for (int e = 0; e < NH; e++) o[e] = sb2[e];

    for (int j = 0; j < HID; j++) {
        float acc = sb1[j];
#pragma unroll
        for (int k = 0; k < 2 * RFF; k++)
            acc = fmaf(feats[k], sW1[k * HID + j], acc);
        // exact gelu: x * 0.5 * (1 + erf(x / sqrt(2)))
        const float h = 0.5f * acc * (1.0f + erff(acc * 0.70710678118654752440f));
#pragma unroll
        for (int e = 0; e < NH; e++)
            o[e] = fmaf(h, sW2[j * NH + e], o[e]);
    }

#pragma unroll
    for (int e = 0; e < NH; e++) g_tbl[node * NH + e] = o[e];
}

// ---------------------------------------------------------------------------
// Main kernel: one block per (b, t) row; 8 warps each cover 64 s-values.
// 4 lanes cooperate per (t,s) pair: lane part p owns heads 4p..4p+3.
// Each lane: 2 x LDG.128 from the pair's contiguous 128B LUT region, lerp,
// write 4 head planes.
// ---------------------------------------------------------------------------
__global__ void __launch_bounds__(256) bias_kernel(
    const float* __restrict__ centers,   // [B*T]
    const int*   __restrict__ mask,      // [B*T] bool stored as int32
    float* __restrict__ out)             // [B, NH, T, T]
{
    const int row = blockIdx.x;        // 0 .. B*T-1
    const int b = row >> 9;            // / T
    const int t = row & (TT - 1);

    const float ct = centers[row];
    const bool  mt = (mask[row] != 0);

    const int lane = threadIdx.x & 31;
    const int warp = threadIdx.x >> 5; // 0..7
    const int sub  = lane >> 2;        // pair within group of 8
    const int part = lane & 3;         // head quadrant 0..3

    const float* __restrict__ cb = centers + b * TT;
    const int*   __restrict__ mb = mask + b * TT;
    float* __restrict__ outb = out + ((size_t)b * NH * TT + (size_t)t) * TT;

    const size_t plane = (size_t)TT * TT;
    float* __restrict__ oh = outb + (size_t)(part * 4) * plane;

#pragma unroll
    for (int step = 0; step < 8; step++) {
        const int s = warp * 64 + step * 8 + sub;
        const float cs = cb[s];
        const float m = (mt && (mb[s] != 0)) ? 1.0f : 0.0f;

        const float d = fabsf(ct - cs);
        const float u = d * (float)TBL_N;
        int i = (int)u;
        i = min(i, TBL_N - 1);
        const float frac = u - (float)i;

        const float4* reg = reinterpret_cast<const float4*>(g_tbl + (size_t)i * NH);
        const float4 A  = __ldg(&reg[part]);       // row i,   heads 4p..4p+3
        const float4 Bv = __ldg(&reg[part + 4]);   // row i+1, heads 4p..4p+3

        float4 r;
        r.x = fmaf(frac, Bv.x - A.x, A.x) * m;
        r.y = fmaf(frac, Bv.y - A.y, A.y) * m;
        r.z = fmaf(frac, Bv.z - A.z, A.z) * m;
        r.w = fmaf(frac, Bv.w - A.w, A.w) * m;

        float* o = oh + s;
        o[0]         = r.x;
        o[plane]     = r.y;
        o[2 * plane] = r.z;
        o[3 * plane] = r.w;
    }
}

// ---------------------------------------------------------------------------
// Inputs (metadata order): centers01 [8,512] f32, mask [8,512] bool(int32),
// bias_phase [16] f32, W1 [32,64] f32, b1 [64] f32, W2 [64,16] f32, b2 [16] f32.
// Output: [8,16,512,512] f32.
// ---------------------------------------------------------------------------
extern "C" void kernel_launch(void* const* d_in, const int* in_sizes, int n_in,
                              void* d_out, int out_size)
{
    const float* centers = (const float*)d_in[0];
    const int*   mask    = (const int*)d_in[1];
    const float* phase   = (const float*)d_in[2];
    const float* W1      = (const float*)d_in[3];
    const float* b1      = (const float*)d_in[4];
    const float* W2      = (const float*)d_in[5];
    const float* b2      = (const float*)d_in[6];
    float*       out     = (float*)d_out;

    build_table_kernel<<<(TBL_N + 1 + 255) / 256, 256>>>(phase, W1, b1, W2, b2);
    bias_kernel<<<BB * TT, 256>>>(centers, mask, out);
}

// round 3
// speedup vs baseline: 1.0005x; 1.0005x over previous
#include <cuda_runtime.h>
#include <math.h>

#define BB 8
#define TT 512
#define RFF 16
#define HID 64
#define NH 16
#define TBL_N 16384   /* intervals; nodes 0..TBL_N inclusive */
#define TWO_PI_F 6.283185307179586f

// LUT: g_tbl[node][head], 16 fp32 per row (64B). (TBL_N + 2) rows so the
// top index can still read rows i and i+1.
__device__ __align__(128) static float g_tbl[(TBL_N + 2) * NH];

// ---------------------------------------------------------------------------
// Build kernel: 4 lanes per node; lane q computes hidden units [16q, 16q+16),
// partial 16-head outputs are summed across the quartet with xor-shuffles.
// ---------------------------------------------------------------------------
__global__ void __launch_bounds__(256) build_table_kernel(
    const float* __restrict__ phase,   // [16]
    const float* __restrict__ W1,      // [32,64]
    const float* __restrict__ b1,      // [64]
    const float* __restrict__ W2,      // [64,16]
    const float* __restrict__ b2)      // [16]
{
    __shared__ float sW1[2 * RFF * HID];
    __shared__ float sW2[HID * NH];
    __shared__ float sb1[HID];
    __shared__ float sb2[NH];
    __shared__ float sph[RFF];

    const int tid = threadIdx.x;
    for (int i = tid; i < 2 * RFF * HID; i += blockDim.x) sW1[i] = W1[i];
    for (int i = tid; i < HID * NH;     i += blockDim.x) sW2[i] = W2[i];
    if (tid < HID) sb1[tid] = b1[tid];
    if (tid < NH)  sb2[tid] = b2[tid];
    if (tid < RFF) sph[tid] = phase[tid];
    __syncthreads();

    const int gid = blockIdx.x * blockDim.x + tid;
    int node = gid >> 2;
    const int q = gid & 3;
    if (node > TBL_N) node = TBL_N;   // clamp: duplicates write identical data

    const float d = (float)node * (1.0f / (float)TBL_N);

    // RFF frequencies: logspace(log10 2, log10 64, 16) = 2^(1 + k/3)
    float feats[2 * RFF];
#pragma unroll
    for (int k = 0; k < RFF; k++) {
        const float f = exp2f(1.0f + (float)k * (1.0f / 3.0f));
        const float a = fmaf(TWO_PI_F * f, d, sph[k]);
        float s, c;
        sincosf(a, &s, &c);
        feats[k]       = s;
        feats[RFF + k] = c;
    }

    float o[NH];
#pragma unroll
    for (int e = 0; e < NH; e++) o[e] = (q == 0) ? sb2[e] : 0.0f;

    const int j0 = q * (HID / 4);
#pragma unroll 2
    for (int jj = 0; jj < HID / 4; jj++) {
        const int j = j0 + jj;
        float acc = sb1[j];
#pragma unroll
        for (int k = 0; k < 2 * RFF; k++)
            acc = fmaf(feats[k], sW1[k * HID + j], acc);
        // exact gelu: x * 0.5 * (1 + erf(x / sqrt(2)))
        const float h = 0.5f * acc * (1.0f + erff(acc * 0.70710678118654752440f));
#pragma unroll
        for (int e = 0; e < NH; e++)
            o[e] = fmaf(h, sW2[j * NH + e], o[e]);
    }

    // sum partials across the 4-lane quartet (stays inside a warp)
#pragma unroll
    for (int e = 0; e < NH; e++) {
        o[e] += __shfl_xor_sync(0xffffffffu, o[e], 1);
        o[e] += __shfl_xor_sync(0xffffffffu, o[e], 2);
    }

    // lane q writes heads 4q..4q+3
    float4 v;
    if      (q == 0) v = make_float4(o[0],  o[1],  o[2],  o[3]);
    else if (q == 1) v = make_float4(o[4],  o[5],  o[6],  o[7]);
    else if (q == 2) v = make_float4(o[8],  o[9],  o[10], o[11]);
    else             v = make_float4(o[12], o[13], o[14], o[15]);
    reinterpret_cast<float4*>(g_tbl + (size_t)node * NH)[q] = v;
}

// ---------------------------------------------------------------------------
// Main kernel: one block per (b, t) row.
// Phase 1: 4 lanes per (t,s) pair lerp 4 heads each from the LUT into smem.
// Phase 2: contiguous float4 reads from smem -> fully coalesced 128B streaming
//          stores, one plane segment per warp iteration.
// ---------------------------------------------------------------------------
#define SPAD 516   /* 512 + 4 words row pitch (16B-aligned, de-conflicts) */

__global__ void __launch_bounds__(256) bias_kernel(
    const float* __restrict__ centers,   // [B*T]
    const int*   __restrict__ mask,      // [B*T] bool stored as int32
    float* __restrict__ out)             // [B, NH, T, T]
{
    __shared__ float sbuf[NH * SPAD];

    const int row = blockIdx.x;        // 0 .. B*T-1
    const int b = row >> 9;
    const int t = row & (TT - 1);

    const float ct = centers[row];
    const bool  mt = (mask[row] != 0);

    const int lane = threadIdx.x & 31;
    const int warp = threadIdx.x >> 5;
    const int sub  = lane >> 2;        // pair within group of 8
    const int part = lane & 3;         // head quadrant

    const float* __restrict__ cb = centers + b * TT;
    const int*   __restrict__ mb = mask + b * TT;

#pragma unroll
    for (int step = 0; step < 8; step++) {
        const int s = warp * 64 + step * 8 + sub;
        const float cs = cb[s];
        const float m = (mt && (mb[s] != 0)) ? 1.0f : 0.0f;

        const float d = fabsf(ct - cs);
        const float u = d * (float)TBL_N;
        int i = (int)u;
        i = min(i, TBL_N - 1);
        const float frac = u - (float)i;

        const float4* reg = reinterpret_cast<const float4*>(g_tbl + (size_t)i * NH);
        const float4 A  = __ldg(&reg[part]);       // row i,   heads 4p..4p+3
        const float4 Bv = __ldg(&reg[part + 4]);   // row i+1, heads 4p..4p+3

        float* sb = sbuf + (4 * part) * SPAD + s;
        sb[0 * SPAD] = fmaf(frac, Bv.x - A.x, A.x) * m;
        sb[1 * SPAD] = fmaf(frac, Bv.y - A.y, A.y) * m;
        sb[2 * SPAD] = fmaf(frac, Bv.z - A.z, A.z) * m;
        sb[3 * SPAD] = fmaf(frac, Bv.w - A.w, A.w) * m;
    }

    __syncthreads();

    // Phase 2: 2048 float4 segments (16 planes x 128), coalesced streaming stores
    float* __restrict__ outb = out + ((size_t)b * NH * TT + (size_t)t) * TT;
    const size_t plane = (size_t)TT * TT;

#pragma unroll
    for (int it = 0; it < 8; it++) {
        const int v = it * 256 + threadIdx.x;   // 0..2047
        const int h = v >> 7;                   // plane
        const int k = v & 127;                  // float4 index within plane row
        const float4 val = *reinterpret_cast<const float4*>(sbuf + h * SPAD + 4 * k);
        __stcs(reinterpret_cast<float4*>(outb + (size_t)h * plane) + k, val);
    }
}

// ---------------------------------------------------------------------------
// Inputs (metadata order): centers01 [8,512] f32, mask [8,512] bool(int32),
// bias_phase [16] f32, W1 [32,64] f32, b1 [64] f32, W2 [64,16] f32, b2 [16] f32.
// Output: [8,16,512,512] f32.
// ---------------------------------------------------------------------------
extern "C" void kernel_launch(void* const* d_in, const int* in_sizes, int n_in,
                              void* d_out, int out_size)
{
    const float* centers = (const float*)d_in[0];
    const int*   mask    = (const int*)d_in[1];
    const float* phase   = (const float*)d_in[2];
    const float* W1      = (const float*)d_in[3];
    const float* b1      = (const float*)d_in[4];
    const float* W2      = (const float*)d_in[5];
    const float* b2      = (const float*)d_in[6];
    float*       out     = (float*)d_out;

    const int build_threads = (TBL_N + 1) * 4;
    build_table_kernel<<<(build_threads + 255) / 256, 256>>>(phase, W1, b1, W2, b2);
    bias_kernel<<<BB * TT, 256>>>(centers, mask, out);
}

// round 5
// speedup vs baseline: 1.5914x; 1.5907x over previous
#include <cuda_runtime.h>
#include <cuda_fp16.h>
#include <math.h>

#define BB 8
#define TT 512
#define RFF 16
#define HID 64
#define NH 16
#define TBL_N 4096
#define TWO_PI_F 6.283185307179586f
#define INV_SQRT2_F 0.70710678118654752440f
#define INV_SQRT_2PI_F 0.39894228040143267794f

// bit-cast helpers (version-portable)
static __device__ __forceinline__ unsigned h2_as_u32(__half2 h) {
    return *reinterpret_cast<unsigned*>(&h);
}
static __device__ __forceinline__ __half2 u32_as_h2(unsigned u) {
    return *reinterpret_cast<__half2*>(&u);
}

// Table: one 64B row per node: [v0..v7, w0..w7, v8..v15, w8..w15] as __half,
// where v = g(x_i), w = g'(x_i)/TBL_N (pre-scaled for node-unit delta).
__device__ __align__(128) static __half g_tbl[(TBL_N + 2) * 2 * NH];

// ---------------------------------------------------------------------------
// Build kernel: 4 lanes per node. Lane q computes hidden units [16q,16q+16),
// producing both value and analytic-derivative partials; quartet shfl-reduce;
// lane q writes one 16B chunk of the 64B row.
// ---------------------------------------------------------------------------
__global__ void __launch_bounds__(256) build_table_kernel(
    const float* __restrict__ phase,   // [16]
    const float* __restrict__ W1,      // [32,64]
    const float* __restrict__ b1,      // [64]
    const float* __restrict__ W2,      // [64,16]
    const float* __restrict__ b2)      // [16]
{
    __shared__ float sW1[2 * RFF * HID];
    __shared__ float sW2[HID * NH];
    __shared__ float sb1[HID];
    __shared__ float sb2[NH];
    __shared__ float sph[RFF];

    const int tid = threadIdx.x;
    for (int i = tid; i < 2 * RFF * HID; i += blockDim.x) sW1[i] = W1[i];
    for (int i = tid; i < HID * NH;     i += blockDim.x) sW2[i] = W2[i];
    if (tid < HID) sb1[tid] = b1[tid];
    if (tid < NH)  sb2[tid] = b2[tid];
    if (tid < RFF) sph[tid] = phase[tid];
    __syncthreads();

    const int gid = blockIdx.x * blockDim.x + tid;
    int node = gid >> 2;
    const int q = gid & 3;
    if (node > TBL_N) node = TBL_N;   // clamp: duplicates write identical data

    const float d = (float)node * (1.0f / (float)TBL_N);

    // freqs = logspace(log10 2, log10 64, 16) = 2^(1 + k/3)
    float fsin[RFF], fcos[RFF], omg[RFF];
#pragma unroll
    for (int k = 0; k < RFF; k++) {
        const float f = exp2f(1.0f + (float)k * (1.0f / 3.0f));
        omg[k] = TWO_PI_F * f;
        const float a = fmaf(omg[k], d, sph[k]);
        sincosf(a, &fsin[k], &fcos[k]);
    }

    float o[NH], od[NH];
#pragma unroll
    for (int e = 0; e < NH; e++) { o[e] = (q == 0) ? sb2[e] : 0.0f; od[e] = 0.0f; }

    const int j0 = q * (HID / 4);
    for (int jj = 0; jj < HID / 4; jj++) {
        const int j = j0 + jj;
        float z = sb1[j], zp = 0.0f;
#pragma unroll
        for (int k = 0; k < RFF; k++) {
            const float ws = sW1[k * HID + j];
            const float wc = sW1[(RFF + k) * HID + j];
            z  = fmaf(fsin[k], ws, z);
            z  = fmaf(fcos[k], wc, z);
            // d/dd sin(a)=omg*cos(a); d/dd cos(a)=-omg*sin(a)
            zp = fmaf(omg[k] * fcos[k], ws, zp);
            zp = fmaf(-omg[k] * fsin[k], wc, zp);
        }
        const float Phi = 0.5f * (1.0f + erff(z * INV_SQRT2_F));
        const float phi = INV_SQRT_2PI_F * expf(-0.5f * z * z);
        const float h  = z * Phi;                 // exact gelu
        const float hp = (Phi + z * phi) * zp;    // d gelu(z)/dd
#pragma unroll
        for (int e = 0; e < NH; e++) {
            const float w2 = sW2[j * NH + e];
            o[e]  = fmaf(h,  w2, o[e]);
            od[e] = fmaf(hp, w2, od[e]);
        }
    }

    // reduce partials across the quartet (lanes differ only in bits 0,1)
#pragma unroll
    for (int e = 0; e < NH; e++) {
        o[e]  += __shfl_xor_sync(0xffffffffu, o[e],  1);
        o[e]  += __shfl_xor_sync(0xffffffffu, o[e],  2);
        od[e] += __shfl_xor_sync(0xffffffffu, od[e], 1);
        od[e] += __shfl_xor_sync(0xffffffffu, od[e], 2);
    }

    // chunk q of the row: q0 = v[0..7], q1 = w[0..7], q2 = v[8..15], q3 = w[8..15]
    const float dscale = 1.0f / (float)TBL_N;
    float src[8];
#pragma unroll
    for (int c = 0; c < 8; c++) {
        const int base = (q & 2) ? 8 : 0;
        src[c] = (q & 1) ? od[base + c] * dscale : o[base + c];
    }
    uint4 pk;
    pk.x = h2_as_u32(__floats2half2_rn(src[0], src[1]));
    pk.y = h2_as_u32(__floats2half2_rn(src[2], src[3]));
    pk.z = h2_as_u32(__floats2half2_rn(src[4], src[5]));
    pk.w = h2_as_u32(__floats2half2_rn(src[6], src[7]));
    reinterpret_cast<uint4*>(g_tbl + (size_t)node * 2 * NH)[q] = pk;
}

// ---------------------------------------------------------------------------
// Main kernel: one block per (b, t); 8 warps x 64 s each.
// 2 lanes per pair (p = lane&1 owns heads 8p..8p+7): 2 x LDG.128 (v+w chunks),
// out = v + w*delta, 8 x STG.32 streaming stores (16 consecutive s per plane
// per warp-group -> 64B/line store wavefronts).
// ---------------------------------------------------------------------------
__global__ void __launch_bounds__(256) bias_kernel(
    const float* __restrict__ centers,   // [B*T]
    const int*   __restrict__ mask,      // [B*T] bool stored as int32
    float* __restrict__ out)             // [B, NH, T, T]
{
    const int row = blockIdx.x;
    const int b = row >> 9;
    const int t = row & (TT - 1);

    const float ct = centers[row];
    const bool  mt = (mask[row] != 0);

    const int lane = threadIdx.x & 31;
    const int warp = threadIdx.x >> 5;
    const int sub  = lane >> 1;        // pair 0..15 within warp-step
    const int p    = lane & 1;         // head half: 8p..8p+7

    const float* __restrict__ cb = centers + b * TT;
    const int*   __restrict__ mb = mask + b * TT;

    const size_t plane = (size_t)TT * TT;
    float* __restrict__ oh =
        out + ((size_t)b * NH * TT + (size_t)t) * TT + (size_t)(8 * p) * plane;

#pragma unroll
    for (int step = 0; step < 4; step++) {
        const int s = warp * 64 + step * 16 + sub;
        const float cs = cb[s];
        const float m = (mt && (mb[s] != 0)) ? 1.0f : 0.0f;

        const float dd = fabsf(ct - cs);
        const float u = dd * (float)TBL_N;
        const int   i = __float2int_rn(u);          // 0..TBL_N
        const float delta = (u - (float)i) * m;     // fold mask into both terms

        const uint4* r = reinterpret_cast<const uint4*>(g_tbl + (size_t)i * 2 * NH);
        const uint4 V = __ldg(r + 2 * p);       // v[8p..8p+7]
        const uint4 W = __ldg(r + 2 * p + 1);   // w[8p..8p+7]

        const unsigned* vp = &V.x;
        const unsigned* wp = &W.x;
        float* o = oh + s;
#pragma unroll
        for (int c = 0; c < 4; c++) {
            const float2 v2 = __half22float2(u32_as_h2(vp[c]));
            const float2 w2 = __half22float2(u32_as_h2(wp[c]));
            const float o0 = fmaf(w2.x, delta, v2.x * m);
            const float o1 = fmaf(w2.y, delta, v2.y * m);
            __stcs(o + (size_t)(2 * c) * plane,     o0);
            __stcs(o + (size_t)(2 * c + 1) * plane, o1);
        }
    }
}

// ---------------------------------------------------------------------------
// Inputs (metadata order): centers01 [8,512] f32, mask [8,512] bool(int32),
// bias_phase [16] f32, W1 [32,64] f32, b1 [64] f32, W2 [64,16] f32, b2 [16] f32.
// Output: [8,16,512,512] f32.
// ---------------------------------------------------------------------------
extern "C" void kernel_launch(void* const* d_in, const int* in_sizes, int n_in,
                              void* d_out, int out_size)
{
    const float* centers = (const float*)d_in[0];
    const int*   mask    = (const int*)d_in[1];
    const float* phase   = (const float*)d_in[2];
    const float* W1      = (const float*)d_in[3];
    const float* b1      = (const float*)d_in[4];
    const float* W2      = (const float*)d_in[5];
    const float* b2      = (const float*)d_in[6];
    float*       out     = (float*)d_out;

    const int build_threads = (TBL_N + 1) * 4;
    build_table_kernel<<<(build_threads + 255) / 256, 256>>>(phase, W1, b1, W2, b2);
    bias_kernel<<<BB * TT, 256>>>(centers, mask, out);
}

// round 6
// speedup vs baseline: 1.7070x; 1.0726x over previous
#include <cuda_runtime.h>
#include <cuda_fp16.h>
#include <math.h>

#define BB 8
#define TT 512
#define RFF 16
#define HID 64
#define NH 16
#define TBL_N 4096
#define TWO_PI_F 6.283185307179586f
#define INV_PI_F 0.31830988618379067154f
#define INV_SQRT2_F 0.70710678118654752440f
#define INV_SQRT_2PI_F 0.39894228040143267794f

// bit-cast helpers (version-portable)
static __device__ __forceinline__ unsigned h2_as_u32(__half2 h) {
    return *reinterpret_cast<unsigned*>(&h);
}
static __device__ __forceinline__ __half2 u32_as_h2(unsigned u) {
    return *reinterpret_cast<__half2*>(&u);
}

// Table: one 64B row per node: [v0..v7 | w0..w7 | v8..v15 | w8..w15] as __half,
// where v = g(x_i), w = g'(x_i)/TBL_N (pre-scaled for node-unit delta).
__device__ __align__(128) static __half g_tbl[(TBL_N + 2) * 2 * NH];

// ---------------------------------------------------------------------------
// Build kernel: 4 lanes per node. Lane q computes hidden units [16q,16q+16),
// producing value and analytic-derivative partials; quartet shfl-reduce;
// lane q writes one 16B chunk of the 64B row.
// ---------------------------------------------------------------------------
__global__ void __launch_bounds__(256) build_table_kernel(
    const float* __restrict__ phase,   // [16]
    const float* __restrict__ W1,      // [32,64]
    const float* __restrict__ b1,      // [64]
    const float* __restrict__ W2,      // [64,16]
    const float* __restrict__ b2)      // [16]
{
    __shared__ float sW1[2 * RFF * HID];
    __shared__ float sW2[HID * NH];
    __shared__ float sb1[HID];
    __shared__ float sb2[NH];
    __shared__ float sph[RFF];

    const int tid = threadIdx.x;
    for (int i = tid; i < 2 * RFF * HID; i += blockDim.x) sW1[i] = W1[i];
    for (int i = tid; i < HID * NH;     i += blockDim.x) sW2[i] = W2[i];
    if (tid < HID) sb1[tid] = b1[tid];
    if (tid < NH)  sb2[tid] = b2[tid];
    if (tid < RFF) sph[tid] = phase[tid];
    __syncthreads();

    const int gid = blockIdx.x * blockDim.x + tid;
    int node = gid >> 2;
    const int q = gid & 3;
    if (node > TBL_N) node = TBL_N;   // clamp: duplicates write identical data

    const float d = (float)node * (1.0f / (float)TBL_N);

    // freqs = logspace(log10 2, log10 64, 16) = 2^(1 + k/3)
    // sin(2*pi*f*d + phi) = sin(pi * (2*f*d + phi/pi))  -> sincospif (exact
    // range reduction, much cheaper than sincosf at args up to ~400 rad)
    float fsin[RFF], fcos[RFF], omg[RFF];
#pragma unroll
    for (int k = 0; k < RFF; k++) {
        const float f = exp2f(1.0f + (float)k * (1.0f / 3.0f));
        omg[k] = TWO_PI_F * f;
        const float y = fmaf(2.0f * f, d, sph[k] * INV_PI_F);
        sincospif(y, &fsin[k], &fcos[k]);
    }

    float o[NH], od[NH];
#pragma unroll
    for (int e = 0; e < NH; e++) { o[e] = (q == 0) ? sb2[e] : 0.0f; od[e] = 0.0f; }

    const int j0 = q * (HID / 4);
    for (int jj = 0; jj < HID / 4; jj++) {
        const int j = j0 + jj;
        float z = sb1[j], zp = 0.0f;
#pragma unroll
        for (int k = 0; k < RFF; k++) {
            const float ws = sW1[k * HID + j];
            const float wc = sW1[(RFF + k) * HID + j];
            z  = fmaf(fsin[k], ws, z);
            z  = fmaf(fcos[k], wc, z);
            zp = fmaf(omg[k] * fcos[k], ws, zp);
            zp = fmaf(-omg[k] * fsin[k], wc, zp);
        }
        const float Phi = 0.5f * (1.0f + erff(z * INV_SQRT2_F));
        const float phi = INV_SQRT_2PI_F * __expf(-0.5f * z * z);
        const float h  = z * Phi;                 // exact gelu
        const float hp = (Phi + z * phi) * zp;    // d gelu(z)/dd
#pragma unroll
        for (int e = 0; e < NH; e++) {
            const float w2 = sW2[j * NH + e];
            o[e]  = fmaf(h,  w2, o[e]);
            od[e] = fmaf(hp, w2, od[e]);
        }
    }

    // reduce partials across the quartet (lanes differ only in bits 0,1)
#pragma unroll
    for (int e = 0; e < NH; e++) {
        o[e]  += __shfl_xor_sync(0xffffffffu, o[e],  1);
        o[e]  += __shfl_xor_sync(0xffffffffu, o[e],  2);
        od[e] += __shfl_xor_sync(0xffffffffu, od[e], 1);
        od[e] += __shfl_xor_sync(0xffffffffu, od[e], 2);
    }

    // chunk q of the row: q0 = v[0..7], q1 = w[0..7], q2 = v[8..15], q3 = w[8..15]
    const float dscale = 1.0f / (float)TBL_N;
    float src[8];
#pragma unroll
    for (int c = 0; c < 8; c++) {
        const int base = (q & 2) ? 8 : 0;
        src[c] = (q & 1) ? od[base + c] * dscale : o[base + c];
    }
    uint4 pk;
    pk.x = h2_as_u32(__floats2half2_rn(src[0], src[1]));
    pk.y = h2_as_u32(__floats2half2_rn(src[2], src[3]));
    pk.z = h2_as_u32(__floats2half2_rn(src[4], src[5]));
    pk.w = h2_as_u32(__floats2half2_rn(src[6], src[7]));
    reinterpret_cast<uint4*>(g_tbl + (size_t)node * 2 * NH)[q] = pk;
}

// ---------------------------------------------------------------------------
// Main kernel: one block per (b, t); 8 warps x 64 s each.
// 2 lanes per pair (p = lane&1 owns heads 8p..8p+7). ONE 256-bit load per
// lane (sm_100+ ld.global.v8.b32) fetches the full 32B [v, w] chunk in a
// single instruction -> one L1 wavefront set per pair instead of two.
// 8 streaming STG.32 per lane (16 consecutive s per plane per instruction).
// ---------------------------------------------------------------------------
__global__ void __launch_bounds__(256) bias_kernel(
    const float* __restrict__ centers,   // [B*T]
    const int*   __restrict__ mask,      // [B*T] bool stored as int32
    float* __restrict__ out)             // [B, NH, T, T]
{
    const int row = blockIdx.x;
    const int b = row >> 9;
    const int t = row & (TT - 1);

    const float ct = centers[row];
    const bool  mt = (mask[row] != 0);

    const int lane = threadIdx.x & 31;
    const int warp = threadIdx.x >> 5;
    const int sub  = lane >> 1;        // pair 0..15 within warp-step
    const int p    = lane & 1;         // head half: 8p..8p+7

    const float* __restrict__ cb = centers + b * TT;
    const int*   __restrict__ mb = mask + b * TT;

    const size_t plane = (size_t)TT * TT;
    float* __restrict__ oh =
        out + ((size_t)b * NH * TT + (size_t)t) * TT + (size_t)(8 * p) * plane;

#pragma unroll
    for (int step = 0; step < 4; step++) {
        const int s = warp * 64 + step * 16 + sub;
        const float cs = cb[s];
        const float m = (mt && (mb[s] != 0)) ? 1.0f : 0.0f;

        const float dd = fabsf(ct - cs);
        const float u = dd * (float)TBL_N;
        const int   i = __float2int_rn(u);          // 0..TBL_N
        const float delta = (u - (float)i) * m;     // fold mask into both terms

        // 32B chunk for this lane: [v(8p..8p+7) | w(8p..8p+7)] as 16 halves
        const __half* rowp = g_tbl + (size_t)i * 2 * NH + 16 * p;
        unsigned r0, r1, r2, r3, r4, r5, r6, r7;
        asm("ld.global.v8.b32 {%0,%1,%2,%3,%4,%5,%6,%7}, [%8];"
            : "=r"(r0), "=r"(r1), "=r"(r2), "=r"(r3),
              "=r"(r4), "=r"(r5), "=r"(r6), "=r"(r7)
            : "l"(rowp));
        unsigned vv[4] = {r0, r1, r2, r3};
        unsigned ww[4] = {r4, r5, r6, r7};

        float* o = oh + s;
#pragma unroll
        for (int c = 0; c < 4; c++) {
            const float2 v2 = __half22float2(u32_as_h2(vv[c]));
            const float2 w2 = __half22float2(u32_as_h2(ww[c]));
            const float o0 = fmaf(w2.x, delta, v2.x * m);
            const float o1 = fmaf(w2.y, delta, v2.y * m);
            __stcs(o + (size_t)(2 * c) * plane,     o0);
            __stcs(o + (size_t)(2 * c + 1) * plane, o1);
        }
    }
}

// ---------------------------------------------------------------------------
// Inputs (metadata order): centers01 [8,512] f32, mask [8,512] bool(int32),
// bias_phase [16] f32, W1 [32,64] f32, b1 [64] f32, W2 [64,16] f32, b2 [16] f32.
// Output: [8,16,512,512] f32.
// ---------------------------------------------------------------------------
extern "C" void kernel_launch(void* const* d_in, const int* in_sizes, int n_in,
                              void* d_out, int out_size)
{
    const float* centers = (const float*)d_in[0];
    const int*   mask    = (const int*)d_in[1];
    const float* phase   = (const float*)d_in[2];
    const float* W1      = (const float*)d_in[3];
    const float* b1      = (const float*)d_in[4];
    const float* W2      = (const float*)d_in[5];
    const float* b2      = (const float*)d_in[6];
    float*       out     = (float*)d_out;

    const int build_threads = (TBL_N + 1) * 4;
    build_table_kernel<<<(build_threads + 255) / 256, 256>>>(phase, W1, b1, W2, b2);
    bias_kernel<<<BB * TT, 256>>>(centers, mask, out);
}